// round 16
// baseline (speedup 1.0000x reference)
#include <cuda_runtime.h>
#include <cuda_fp16.h>
#include <stdint.h>
#include <math.h>

#define SEQ 4096
#define HID 2048
#define NH  16
#define HD  128

// ---------------- scratch (device globals; no allocation allowed) ----------
__device__ __half g_ah[SEQ * HID];          // activation single fp16 (x)
__device__ __half g_wh[4 * HID * HID];      // weight^T single fp16 [N][K] x4
__device__ __half g_qh[SEQ * HID];          // Q (normed, roped, scaled) fp16
__device__ __half g_kh[SEQ * HID];          // K (normed, roped) fp16
__device__ __half g_vh[SEQ * HID];          // V single fp16
__device__ __half g_ch[SEQ * HID];          // ctx single fp16
__device__ float2 g_tab[SEQ * 64];          // RoPE (cos, sin) per (pos, pair)

// ---------------- helpers ---------------------------------------------------
__device__ __forceinline__ uint32_t smem_u32(const void* p) {
    uint32_t a;
    asm("{ .reg .u64 t; cvta.to.shared.u64 t, %1; cvt.u32.u64 %0, t; }"
        : "=r"(a) : "l"(p));
    return a;
}
__device__ __forceinline__ void mma_f16(float c[4], const uint32_t a[4],
                                        const uint32_t b[2]) {
    asm volatile(
        "mma.sync.aligned.m16n8k16.row.col.f32.f16.f16.f32 "
        "{%0,%1,%2,%3},{%4,%5,%6,%7},{%8,%9},{%0,%1,%2,%3};"
        : "+f"(c[0]), "+f"(c[1]), "+f"(c[2]), "+f"(c[3])
        : "r"(a[0]), "r"(a[1]), "r"(a[2]), "r"(a[3]), "r"(b[0]), "r"(b[1]));
}
__device__ __forceinline__ void ldsm4(uint32_t r[4], uint32_t addr) {
    asm volatile("ldmatrix.sync.aligned.m8n8.x4.shared.b16 {%0,%1,%2,%3}, [%4];"
                 : "=r"(r[0]), "=r"(r[1]), "=r"(r[2]), "=r"(r[3]) : "r"(addr));
}
__device__ __forceinline__ void ldsm4t(uint32_t r[4], uint32_t addr) {
    asm volatile(
        "ldmatrix.sync.aligned.m8n8.x4.trans.shared.b16 {%0,%1,%2,%3}, [%4];"
        : "=r"(r[0]), "=r"(r[1]), "=r"(r[2]), "=r"(r[3]) : "r"(addr));
}
__device__ __forceinline__ uint32_t pack2h(float x, float y) {
    __half2 p = __floats2half2_rn(x, y);
    return *(uint32_t*)&p;
}
__device__ __forceinline__ void cpasync16(uint32_t dst, const void* src) {
    asm volatile("cp.async.cg.shared.global [%0], [%1], 16;"
                 :: "r"(dst), "l"(src) : "memory");
}
#define CP_COMMIT() asm volatile("cp.async.commit_group;" ::: "memory")
#define CP_WAIT(n)  asm volatile("cp.async.wait_group %0;" :: "n"(n) : "memory")

// ---------------- RoPE table: tab[s][j] = (cos, sin)(pos[s] * f_j) ----------
__global__ __launch_bounds__(64) void rope_tab(const int* __restrict__ pos,
                                               float2* __restrict__ tab)
{
    const int s = blockIdx.x;
    const int j = threadIdx.x;          // pair index 0..63
    const float Cf = 9.210340371976184f / 64.0f;
    float f = __expf(-(float)j * Cf);
    float p = (float)pos[s];
    float sn, cs;
    sincosf(p * f, &sn, &cs);
    tab[s * 64 + j] = make_float2(cs, sn);
}

// ---------------- convert: fp32 -> fp16 single ------------------------------
__global__ __launch_bounds__(256) void conv_h(const float* __restrict__ x,
                                              __half* __restrict__ o, int n)
{
    int i = (blockIdx.x * 256 + threadIdx.x) * 4;
    if (i >= n) return;
    float4 v = *(const float4*)(x + i);
    *(uint2*)(o + i) = make_uint2(pack2h(v.x, v.y), pack2h(v.z, v.w));
}

// ---------------- convert: W[K,N] fp32 -> W^T[N,K] fp16 (z-batched) ---------
__global__ __launch_bounds__(256) void conv_wt(
    const float* __restrict__ w0, const float* __restrict__ w1,
    const float* __restrict__ w2, const float* __restrict__ w3,
    __half* __restrict__ ht)
{
    __shared__ float tile[32][33];
    const int tx = threadIdx.x, ty = threadIdx.y;
    const int n0 = blockIdx.x * 32, k0 = blockIdx.y * 32;
    const int z  = blockIdx.z;
    const float* w = (z == 0) ? w0 : (z == 1) ? w1 : (z == 2) ? w2 : w3;
    const size_t zo = (size_t)z * HID * HID;
#pragma unroll
    for (int i = 0; i < 4; i++) {
        int k = ty + i * 8;
        tile[k][tx] = w[(size_t)(k0 + k) * HID + n0 + tx];
    }
    __syncthreads();
#pragma unroll
    for (int i = 0; i < 4; i++) {
        int n = ty + i * 8;
        ht[zo + (size_t)(n0 + n) * HID + k0 + tx] = __float2half_rn(tile[tx][n]);
    }
}

// ---------------- fp16 GEMM 256x128 + optional fused RMSNorm/RoPE -----------
// Block 256x128, BK=32, 256 threads = 8 warps (4m x 2n), warp tile 64x64.
// fuse==1: z==0 -> RMS+RoPE+scale -> Qh; z==1 -> RMS+RoPE -> Kh; z==2 -> Vh.
// fuse==0: z==0 -> fp32 Cout.
#define GAS 40
#define GSTAGE ((256 + 128) * GAS)
#define GEMM_SMEM (2 * GSTAGE * 2)             // 61440 B
#define NCH (HID / 32)

__global__ __launch_bounds__(256) void gemm_f16(
    const __half* __restrict__ A_g, const __half* __restrict__ B_g,
    float* __restrict__ Cout,
    __half* __restrict__ Qh, __half* __restrict__ Kh, __half* __restrict__ Vh,
    const float2* __restrict__ tab,
    const float* __restrict__ qw, const float* __restrict__ kw,
    int fuse)
{
    extern __shared__ __half sm[];

    const int tid  = threadIdx.x;
    const int warp = tid >> 5;
    const int lane = tid & 31;
    const int g    = lane >> 2;
    const int t    = lane & 3;
    const int wm   = warp >> 1;
    const int wn   = warp & 1;
    const int bx   = blockIdx.x * 128;
    const int by   = blockIdx.y * 256;
    const int z    = blockIdx.z;

    const __half* B_z = B_g + (size_t)z * HID * HID;

    const uint32_t base = smem_u32(sm);

    const int mat  = lane >> 3;
    const int arow = (lane & 7) + 8 * (mat & 1);
    const int acol8 = 8 * (mat >> 1);
    const int brow = (lane & 7) + 8 * (mat >> 1);
    const int bcol8 = 8 * (mat & 1);

    auto stage_load = [&](int s, int k0) {
        uint32_t sb = base + (uint32_t)s * GSTAGE * 2;
#pragma unroll
        for (int i = 0; i < 4; i++) {
            int v = tid + i * 256;
            int r = v >> 2, c = v & 3;
            cpasync16(sb + (uint32_t)(r * GAS) * 2 + c * 16,
                      A_g + (size_t)(by + r) * HID + k0 + c * 8);
        }
#pragma unroll
        for (int i = 0; i < 2; i++) {
            int v = tid + i * 256;
            int r = v >> 2, c = v & 3;
            cpasync16(sb + (uint32_t)((256 + r) * GAS) * 2 + c * 16,
                      B_z + (size_t)(bx + r) * HID + k0 + c * 8);
        }
    };

    float acc[4][8][4] = {};

    stage_load(0, 0);
    CP_COMMIT();

    for (int ch = 0; ch < NCH; ch++) {
        if (ch + 1 < NCH) {
            stage_load((ch + 1) & 1, (ch + 1) * 32);
            CP_COMMIT();
            CP_WAIT(1);
        } else {
            CP_WAIT(0);
        }
        __syncthreads();

        const uint32_t sb = base + (uint32_t)(ch & 1) * GSTAGE * 2;
        const uint32_t aBase = sb;
        const uint32_t bBase = sb + 256 * GAS * 2;

#pragma unroll
        for (int kt = 0; kt < 2; kt++) {
            uint32_t a_f[4][4];
#pragma unroll
            for (int mt = 0; mt < 4; mt++) {
                uint32_t off = ((wm * 64 + mt * 16 + arow) * GAS + kt * 16 + acol8) * 2;
                ldsm4(a_f[mt], aBase + off);
            }
            uint32_t b_f[8][2];
#pragma unroll
            for (int p = 0; p < 4; p++) {
                uint32_t off = ((wn * 64 + p * 16 + brow) * GAS + kt * 16 + bcol8) * 2;
                uint32_t r4[4];
                ldsm4(r4, bBase + off);
                b_f[2 * p][0] = r4[0]; b_f[2 * p][1] = r4[1];
                b_f[2 * p + 1][0] = r4[2]; b_f[2 * p + 1][1] = r4[3];
            }
#pragma unroll
            for (int mt = 0; mt < 4; mt++)
#pragma unroll
                for (int nt = 0; nt < 8; nt++)
                    mma_f16(acc[mt][nt], a_f[mt], b_f[nt]);
        }
        __syncthreads();
    }

    // ---------------- epilogue ----------------
    if (z == 2) {
        // V: plain fp16 store
#pragma unroll
        for (int mt = 0; mt < 4; mt++)
#pragma unroll
            for (int nt = 0; nt < 8; nt++) {
                int row = by + wm * 64 + mt * 16 + g;
                int col = bx + wn * 64 + nt * 8 + 2 * t;
                *(uint32_t*)(Vh + (size_t)row * HID + col) =
                    pack2h(acc[mt][nt][0], acc[mt][nt][1]);
                *(uint32_t*)(Vh + (size_t)(row + 8) * HID + col) =
                    pack2h(acc[mt][nt][2], acc[mt][nt][3]);
            }
        return;
    }

    if (!fuse) {
        // plain fp32 store (out projection)
#pragma unroll
        for (int mt = 0; mt < 4; mt++)
#pragma unroll
            for (int nt = 0; nt < 8; nt++) {
                int row = by + wm * 64 + mt * 16 + g;
                int col = bx + wn * 64 + nt * 8 + 2 * t;
                *(float2*)(Cout + (size_t)row * HID + col) =
                    make_float2(acc[mt][nt][0], acc[mt][nt][1]);
                *(float2*)(Cout + (size_t)(row + 8) * HID + col) =
                    make_float2(acc[mt][nt][2], acc[mt][nt][3]);
            }
        return;
    }

    // ---- fused RMSNorm + RoPE (tile cols = one full head) ----
    float* sred = (float*)sm;   // [256][2] partial sums
    float ssv[4][2];
#pragma unroll
    for (int mt = 0; mt < 4; mt++)
#pragma unroll
        for (int half = 0; half < 2; half++) {
            float ps = 0.f;
#pragma unroll
            for (int nt = 0; nt < 8; nt++) {
                float a0 = acc[mt][nt][half * 2];
                float a1 = acc[mt][nt][half * 2 + 1];
                ps += a0 * a0 + a1 * a1;
            }
            ps += __shfl_xor_sync(0xffffffffu, ps, 1);
            ps += __shfl_xor_sync(0xffffffffu, ps, 2);
            if (t == 0)
                sred[(wm * 64 + mt * 16 + half * 8 + g) * 2 + wn] = ps;
        }
    __syncthreads();
#pragma unroll
    for (int mt = 0; mt < 4; mt++)
#pragma unroll
        for (int half = 0; half < 2; half++) {
            int rl = wm * 64 + mt * 16 + half * 8 + g;
            float ss = sred[rl * 2] + sred[rl * 2 + 1];
            ssv[mt][half] = rsqrtf(ss * (1.0f / 128.0f) + 1e-6f);
        }

    const float scale = 0.08838834764831845f;
    const float* wvec = (z == 0) ? qw : kw;
    __half* dst = (z == 0) ? Qh : Kh;
#pragma unroll
    for (int nt = 0; nt < 8; nt++) {
        int d0 = wn * 64 + nt * 8 + 2 * t;
        float w0 = wvec[d0], w1 = wvec[d0 + 1];
        int pr = d0 >> 1;
#pragma unroll
        for (int mt = 0; mt < 4; mt++)
#pragma unroll
            for (int half = 0; half < 2; half++) {
                int row = by + wm * 64 + mt * 16 + half * 8 + g;
                float r = ssv[mt][half];
                float2 cs = tab[(size_t)row * 64 + pr];
                float x0 = acc[mt][nt][half * 2] * (r * w0);
                float x1 = acc[mt][nt][half * 2 + 1] * (r * w1);
                float o0 = x0 * cs.x - x1 * cs.y;
                float o1 = x0 * cs.y + x1 * cs.x;
                if (z == 0) { o0 *= scale; o1 *= scale; }
                *(uint32_t*)(dst + (size_t)row * HID + bx + d0) = pack2h(o0, o1);
            }
    }
}

// ---------------- flash attention: single-term QK and PV --------------------
// Fixed-offset softmax P' = exp(S-4) (|S| <= 11.32 by Cauchy-Schwarz).
#define FS 136
#define QBYTES (128 * FS * 2)                  // 34816
#define KVSTAGE (2 * 64 * FS * 2)              // 34816 (K + V)
#define FLASH_SMEM (QBYTES + 4 * KVSTAGE)      // 174080
#define NIT (SEQ / 64)

__global__ __launch_bounds__(256) void flash_mma(
    const __half* __restrict__ Qh, const __half* __restrict__ Kh,
    const __half* __restrict__ Vh, __half* __restrict__ O)
{
    extern __shared__ __half sm[];

    const int tid  = threadIdx.x;
    const int warp = tid >> 5;
    const int lane = tid & 31;
    const int g    = lane >> 2;
    const int t    = lane & 3;
    const int h    = blockIdx.y;
    const int q0   = blockIdx.x * 128;

    const uint32_t base  = smem_u32(sm);
    const uint32_t qBase = base;

#pragma unroll
    for (int i = 0; i < 8; i++) {
        int v = tid + i * 256;
        int r = v >> 4, c = (v & 15) * 8;
        *(uint4*)(sm + r * FS + c) =
            *(const uint4*)(Qh + (size_t)(q0 + r) * HID + h * HD + c);
    }

    auto kv_load = [&](int s, int kt0) {
        uint32_t sb = base + QBYTES + (uint32_t)s * KVSTAGE;
#pragma unroll
        for (int t2 = 0; t2 < 2; t2++) {
            const char* src = (t2 == 0) ? (const char*)Kh : (const char*)Vh;
#pragma unroll
            for (int i = 0; i < 4; i++) {
                int v = tid + i * 256;
                int r = v >> 4, c = v & 15;
                cpasync16(sb + (uint32_t)(t2 * 64 * FS + r * FS) * 2 + c * 16,
                          src + ((size_t)(kt0 + r) * HID + h * HD) * 2 + c * 16);
            }
        }
    };

    const int wq = warp * 16;
    float o[16][4] = {};
    float l0s = 0.f, l1s = 0.f;

    const int mat  = lane >> 3;
    const int arow = (lane & 7) + 8 * (mat & 1);
    const int acol8 = 8 * (mat >> 1);
    const int brow = (lane & 7) + 8 * (mat >> 1);
    const int bcol8 = 8 * (mat & 1);
    const int vrow = (lane & 7) + 8 * (mat & 1);
    const int vcol8 = 8 * (mat >> 1);

    kv_load(0, 0);
    CP_COMMIT();
    kv_load(1, 64);
    CP_COMMIT();

    __syncthreads();
    uint32_t qf[8][4];
#pragma unroll
    for (int c = 0; c < 8; c++) {
        uint32_t aoff = ((wq + arow) * FS + c * 16 + acol8) * 2;
        ldsm4(qf[c], qBase + aoff);
    }

    for (int it = 0; it < NIT; it++) {
        if (it + 2 < NIT) {
            kv_load((it + 2) & 3, (it + 2) * 64);
            CP_COMMIT();
            CP_WAIT(2);
        } else if (it + 1 < NIT) {
            CP_WAIT(1);
        } else {
            CP_WAIT(0);
        }
        __syncthreads();

        const uint32_t sb = base + QBYTES + (uint32_t)(it & 3) * KVSTAGE;
        const uint32_t kBase = sb;
        const uint32_t vBase = sb + 64 * FS * 2;

        float S[8][4] = {};
#pragma unroll
        for (int c = 0; c < 8; c++) {
#pragma unroll
            for (int p = 0; p < 4; p++) {
                uint32_t boff = ((p * 16 + brow) * FS + c * 16 + bcol8) * 2;
                uint32_t k4[4];
                ldsm4(k4, kBase + boff);
                uint32_t k0[2] = {k4[0], k4[1]}, k1[2] = {k4[2], k4[3]};
                mma_f16(S[2 * p], qf[c], k0);
                mma_f16(S[2 * p + 1], qf[c], k1);
            }
        }

        uint32_t Ph0[8], Ph1[8];
        float s0 = 0.f, s1 = 0.f;
#pragma unroll
        for (int nt = 0; nt < 8; nt++) {
            float p00 = __expf(S[nt][0] - 4.0f);
            float p01 = __expf(S[nt][1] - 4.0f);
            float p10 = __expf(S[nt][2] - 4.0f);
            float p11 = __expf(S[nt][3] - 4.0f);
            s0 += p00 + p01;
            s1 += p10 + p11;
            Ph0[nt] = pack2h(p00, p01);
            Ph1[nt] = pack2h(p10, p11);
        }
        l0s += s0;
        l1s += s1;

#pragma unroll
        for (int c = 0; c < 4; c++) {
            uint32_t A_h[4] = {Ph0[2 * c], Ph1[2 * c], Ph0[2 * c + 1], Ph1[2 * c + 1]};
#pragma unroll
            for (int dd = 0; dd < 8; dd++) {
                uint32_t voff = ((c * 16 + vrow) * FS + dd * 16 + vcol8) * 2;
                uint32_t vh4[4];
                ldsm4t(vh4, vBase + voff);
                uint32_t vh0[2] = {vh4[0], vh4[1]}, vh1[2] = {vh4[2], vh4[3]};
                mma_f16(o[2 * dd], A_h, vh0);
                mma_f16(o[2 * dd + 1], A_h, vh1);
            }
        }
    }

    l0s += __shfl_xor_sync(0xffffffffu, l0s, 1);
    l0s += __shfl_xor_sync(0xffffffffu, l0s, 2);
    l1s += __shfl_xor_sync(0xffffffffu, l1s, 1);
    l1s += __shfl_xor_sync(0xffffffffu, l1s, 2);

    float inv0 = 1.0f / l0s, inv1 = 1.0f / l1s;
    int row0 = q0 + wq + g;
#pragma unroll
    for (int d = 0; d < 16; d++) {
        int col = h * HD + d * 8 + 2 * t;
        *(uint32_t*)(O + (size_t)row0 * HID + col) =
            pack2h(o[d][0] * inv0, o[d][1] * inv0);
        *(uint32_t*)(O + (size_t)(row0 + 8) * HID + col) =
            pack2h(o[d][2] * inv1, o[d][3] * inv1);
    }
}

// ---------------- launch ---------------------------------------------------
extern "C" void kernel_launch(void* const* d_in, const int* in_sizes, int n_in,
                              void* d_out, int out_size)
{
    const float* x   = (const float*)d_in[0];
    const int*   pos = (const int*)d_in[1];
    const float* wq  = (const float*)d_in[2];
    const float* wk  = (const float*)d_in[3];
    const float* wv  = (const float*)d_in[4];
    const float* wo  = (const float*)d_in[5];
    const float* qnw = (const float*)d_in[6];
    const float* knw = (const float*)d_in[7];
    float* out = (float*)d_out;

    __half *ah, *wh, *qh, *kh, *vh, *ch;
    float2* tab;
    cudaGetSymbolAddress((void**)&ah,  g_ah);
    cudaGetSymbolAddress((void**)&wh,  g_wh);
    cudaGetSymbolAddress((void**)&qh,  g_qh);
    cudaGetSymbolAddress((void**)&kh,  g_kh);
    cudaGetSymbolAddress((void**)&vh,  g_vh);
    cudaGetSymbolAddress((void**)&ch,  g_ch);
    cudaGetSymbolAddress((void**)&tab, g_tab);

    cudaFuncSetAttribute(gemm_f16,
                         cudaFuncAttributeMaxDynamicSharedMemorySize, GEMM_SMEM);
    cudaFuncSetAttribute(flash_mma,
                         cudaFuncAttributeMaxDynamicSharedMemorySize, FLASH_SMEM);

    const int NELEM = SEQ * HID;
    const size_t WSZ = (size_t)HID * HID;

    rope_tab<<<SEQ, 64>>>(pos, tab);
    conv_h<<<NELEM / 1024, 256>>>(x, ah, NELEM);
    conv_wt<<<dim3(HID / 32, HID / 32, 4), dim3(32, 8)>>>(wq, wk, wv, wo, wh);

    // QKV projections with fused RMSNorm+RoPE epilogue (q,k) and V->fp16
    gemm_f16<<<dim3(HID / 128, SEQ / 256, 3), 256, GEMM_SMEM>>>(
        ah, wh, out /*unused*/, qh, kh, vh, tab, qnw, knw, 1);

    flash_mma<<<dim3(SEQ / 128, NH), 256, FLASH_SMEM>>>(qh, kh, vh, ch);

    // out projection (plain fp32 epilogue)
    gemm_f16<<<dim3(HID / 128, SEQ / 256, 1), 256, GEMM_SMEM>>>(
        ch, wh + 3 * WSZ, out, qh, kh, vh, tab, qnw, knw, 0);
}

// round 17
// speedup vs baseline: 1.0019x; 1.0019x over previous
#include <cuda_runtime.h>
#include <cuda_fp16.h>
#include <stdint.h>
#include <math.h>

#define SEQ 4096
#define HID 2048
#define NH  16
#define HD  128

// ---------------- scratch (device globals; no allocation allowed) ----------
__device__ __half g_ah[SEQ * HID];          // activation single fp16 (x)
__device__ __half g_wh[4 * HID * HID];      // weight^T single fp16 [N][K] x4
__device__ __half g_qh[SEQ * HID];          // Q (normed, roped, scaled) fp16
__device__ __half g_kh[SEQ * HID];          // K (normed, roped) fp16
__device__ __half g_vh[SEQ * HID];          // V single fp16
__device__ __half g_ch[SEQ * HID];          // ctx single fp16
__device__ float2 g_tab[SEQ * 64];          // RoPE (cos, sin) per (pos, pair)

// ---------------- helpers ---------------------------------------------------
__device__ __forceinline__ uint32_t smem_u32(const void* p) {
    uint32_t a;
    asm("{ .reg .u64 t; cvta.to.shared.u64 t, %1; cvt.u32.u64 %0, t; }"
        : "=r"(a) : "l"(p));
    return a;
}
__device__ __forceinline__ void mma_f16(float c[4], const uint32_t a[4],
                                        const uint32_t b[2]) {
    asm volatile(
        "mma.sync.aligned.m16n8k16.row.col.f32.f16.f16.f32 "
        "{%0,%1,%2,%3},{%4,%5,%6,%7},{%8,%9},{%0,%1,%2,%3};"
        : "+f"(c[0]), "+f"(c[1]), "+f"(c[2]), "+f"(c[3])
        : "r"(a[0]), "r"(a[1]), "r"(a[2]), "r"(a[3]), "r"(b[0]), "r"(b[1]));
}
__device__ __forceinline__ void ldsm4(uint32_t r[4], uint32_t addr) {
    asm volatile("ldmatrix.sync.aligned.m8n8.x4.shared.b16 {%0,%1,%2,%3}, [%4];"
                 : "=r"(r[0]), "=r"(r[1]), "=r"(r[2]), "=r"(r[3]) : "r"(addr));
}
__device__ __forceinline__ void ldsm4t(uint32_t r[4], uint32_t addr) {
    asm volatile(
        "ldmatrix.sync.aligned.m8n8.x4.trans.shared.b16 {%0,%1,%2,%3}, [%4];"
        : "=r"(r[0]), "=r"(r[1]), "=r"(r[2]), "=r"(r[3]) : "r"(addr));
}
__device__ __forceinline__ uint32_t pack2h(float x, float y) {
    __half2 p = __floats2half2_rn(x, y);
    return *(uint32_t*)&p;
}
__device__ __forceinline__ void cpasync16(uint32_t dst, const void* src) {
    asm volatile("cp.async.cg.shared.global [%0], [%1], 16;"
                 :: "r"(dst), "l"(src) : "memory");
}
#define CP_COMMIT() asm volatile("cp.async.commit_group;" ::: "memory")
#define CP_WAIT(n)  asm volatile("cp.async.wait_group %0;" :: "n"(n) : "memory")

// ---------------- RoPE table: tab[s][j] = (cos, sin)(pos[s] * f_j) ----------
__global__ __launch_bounds__(64) void rope_tab(const int* __restrict__ pos,
                                               float2* __restrict__ tab)
{
    const int s = blockIdx.x;
    const int j = threadIdx.x;
    const float Cf = 9.210340371976184f / 64.0f;
    float f = __expf(-(float)j * Cf);
    float p = (float)pos[s];
    float sn, cs;
    sincosf(p * f, &sn, &cs);
    tab[s * 64 + j] = make_float2(cs, sn);
}

// ---------------- convert: fp32 -> fp16 single ------------------------------
__global__ __launch_bounds__(256) void conv_h(const float* __restrict__ x,
                                              __half* __restrict__ o, int n)
{
    int i = (blockIdx.x * 256 + threadIdx.x) * 4;
    if (i >= n) return;
    float4 v = *(const float4*)(x + i);
    *(uint2*)(o + i) = make_uint2(pack2h(v.x, v.y), pack2h(v.z, v.w));
}

// ---------------- convert: W[K,N] fp32 -> W^T[N,K] fp16 (z-batched) ---------
__global__ __launch_bounds__(256) void conv_wt(
    const float* __restrict__ w0, const float* __restrict__ w1,
    const float* __restrict__ w2, const float* __restrict__ w3,
    __half* __restrict__ ht)
{
    __shared__ float tile[32][33];
    const int tx = threadIdx.x, ty = threadIdx.y;
    const int n0 = blockIdx.x * 32, k0 = blockIdx.y * 32;
    const int z  = blockIdx.z;
    const float* w = (z == 0) ? w0 : (z == 1) ? w1 : (z == 2) ? w2 : w3;
    const size_t zo = (size_t)z * HID * HID;
#pragma unroll
    for (int i = 0; i < 4; i++) {
        int k = ty + i * 8;
        tile[k][tx] = w[(size_t)(k0 + k) * HID + n0 + tx];
    }
    __syncthreads();
#pragma unroll
    for (int i = 0; i < 4; i++) {
        int n = ty + i * 8;
        ht[zo + (size_t)(n0 + n) * HID + k0 + tx] = __float2half_rn(tile[tx][n]);
    }
}

// ---------------- fp16 GEMM 256x128, 512 threads (16 warps, 4m x 4n) --------
// Warp tile 64x32. BK=32, 2-stage cp.async.
// fuse==1: z==0 -> RMS+RoPE+scale -> Qh; z==1 -> RMS+RoPE -> Kh; z==2 -> Vh.
// fuse==0: z==0 -> fp32 Cout.
#define GAS 40
#define GSTAGE ((256 + 128) * GAS)
#define GEMM_SMEM (2 * GSTAGE * 2)             // 61440 B
#define NCH (HID / 32)

__global__ __launch_bounds__(512) void gemm_f16(
    const __half* __restrict__ A_g, const __half* __restrict__ B_g,
    float* __restrict__ Cout,
    __half* __restrict__ Qh, __half* __restrict__ Kh, __half* __restrict__ Vh,
    const float2* __restrict__ tab,
    const float* __restrict__ qw, const float* __restrict__ kw,
    int fuse)
{
    extern __shared__ __half sm[];

    const int tid  = threadIdx.x;
    const int warp = tid >> 5;
    const int lane = tid & 31;
    const int g    = lane >> 2;
    const int t    = lane & 3;
    const int wm   = warp >> 2;      // 0..3 : 64 rows
    const int wn   = warp & 3;       // 0..3 : 32 cols
    const int bx   = blockIdx.x * 128;
    const int by   = blockIdx.y * 256;
    const int z    = blockIdx.z;

    const __half* B_z = B_g + (size_t)z * HID * HID;

    const uint32_t base = smem_u32(sm);

    const int mat  = lane >> 3;
    const int arow = (lane & 7) + 8 * (mat & 1);
    const int acol8 = 8 * (mat >> 1);
    const int brow = (lane & 7) + 8 * (mat >> 1);
    const int bcol8 = 8 * (mat & 1);

    auto stage_load = [&](int s, int k0) {
        uint32_t sb = base + (uint32_t)s * GSTAGE * 2;
        // A: 256 rows x 4 chunks = 1024 -> 2 iters of 512
#pragma unroll
        for (int i = 0; i < 2; i++) {
            int v = tid + i * 512;
            int r = v >> 2, c = v & 3;
            cpasync16(sb + (uint32_t)(r * GAS) * 2 + c * 16,
                      A_g + (size_t)(by + r) * HID + k0 + c * 8);
        }
        // B: 128 rows x 4 chunks = 512 -> 1 iter
        {
            int r = tid >> 2, c = tid & 3;
            cpasync16(sb + (uint32_t)((256 + r) * GAS) * 2 + c * 16,
                      B_z + (size_t)(bx + r) * HID + k0 + c * 8);
        }
    };

    float acc[4][4][4] = {};

    stage_load(0, 0);
    CP_COMMIT();

    for (int ch = 0; ch < NCH; ch++) {
        if (ch + 1 < NCH) {
            stage_load((ch + 1) & 1, (ch + 1) * 32);
            CP_COMMIT();
            CP_WAIT(1);
        } else {
            CP_WAIT(0);
        }
        __syncthreads();

        const uint32_t sb = base + (uint32_t)(ch & 1) * GSTAGE * 2;
        const uint32_t aBase = sb;
        const uint32_t bBase = sb + 256 * GAS * 2;

#pragma unroll
        for (int kt = 0; kt < 2; kt++) {
            uint32_t a_f[4][4];
#pragma unroll
            for (int mt = 0; mt < 4; mt++) {
                uint32_t off = ((wm * 64 + mt * 16 + arow) * GAS + kt * 16 + acol8) * 2;
                ldsm4(a_f[mt], aBase + off);
            }
            uint32_t b_f[4][2];
#pragma unroll
            for (int p = 0; p < 2; p++) {
                uint32_t off = ((wn * 32 + p * 16 + brow) * GAS + kt * 16 + bcol8) * 2;
                uint32_t r4[4];
                ldsm4(r4, bBase + off);
                b_f[2 * p][0] = r4[0]; b_f[2 * p][1] = r4[1];
                b_f[2 * p + 1][0] = r4[2]; b_f[2 * p + 1][1] = r4[3];
            }
#pragma unroll
            for (int mt = 0; mt < 4; mt++)
#pragma unroll
                for (int nt = 0; nt < 4; nt++)
                    mma_f16(acc[mt][nt], a_f[mt], b_f[nt]);
        }
        __syncthreads();
    }

    // ---------------- epilogue ----------------
    if (z == 2) {
#pragma unroll
        for (int mt = 0; mt < 4; mt++)
#pragma unroll
            for (int nt = 0; nt < 4; nt++) {
                int row = by + wm * 64 + mt * 16 + g;
                int col = bx + wn * 32 + nt * 8 + 2 * t;
                *(uint32_t*)(Vh + (size_t)row * HID + col) =
                    pack2h(acc[mt][nt][0], acc[mt][nt][1]);
                *(uint32_t*)(Vh + (size_t)(row + 8) * HID + col) =
                    pack2h(acc[mt][nt][2], acc[mt][nt][3]);
            }
        return;
    }

    if (!fuse) {
#pragma unroll
        for (int mt = 0; mt < 4; mt++)
#pragma unroll
            for (int nt = 0; nt < 4; nt++) {
                int row = by + wm * 64 + mt * 16 + g;
                int col = bx + wn * 32 + nt * 8 + 2 * t;
                *(float2*)(Cout + (size_t)row * HID + col) =
                    make_float2(acc[mt][nt][0], acc[mt][nt][1]);
                *(float2*)(Cout + (size_t)(row + 8) * HID + col) =
                    make_float2(acc[mt][nt][2], acc[mt][nt][3]);
            }
        return;
    }

    // ---- fused RMSNorm + RoPE (tile cols = one full head) ----
    float* sred = (float*)sm;   // [256][4] partial sums
    float ssv[4][2];
#pragma unroll
    for (int mt = 0; mt < 4; mt++)
#pragma unroll
        for (int half = 0; half < 2; half++) {
            float ps = 0.f;
#pragma unroll
            for (int nt = 0; nt < 4; nt++) {
                float a0 = acc[mt][nt][half * 2];
                float a1 = acc[mt][nt][half * 2 + 1];
                ps += a0 * a0 + a1 * a1;
            }
            ps += __shfl_xor_sync(0xffffffffu, ps, 1);
            ps += __shfl_xor_sync(0xffffffffu, ps, 2);
            if (t == 0)
                sred[(wm * 64 + mt * 16 + half * 8 + g) * 4 + wn] = ps;
        }
    __syncthreads();
#pragma unroll
    for (int mt = 0; mt < 4; mt++)
#pragma unroll
        for (int half = 0; half < 2; half++) {
            int rl = wm * 64 + mt * 16 + half * 8 + g;
            float ss = (sred[rl * 4] + sred[rl * 4 + 1]) +
                       (sred[rl * 4 + 2] + sred[rl * 4 + 3]);
            ssv[mt][half] = rsqrtf(ss * (1.0f / 128.0f) + 1e-6f);
        }

    const float scale = 0.08838834764831845f;
    const float* wvec = (z == 0) ? qw : kw;
    __half* dst = (z == 0) ? Qh : Kh;
#pragma unroll
    for (int nt = 0; nt < 4; nt++) {
        int d0 = wn * 32 + nt * 8 + 2 * t;
        float w0 = wvec[d0], w1 = wvec[d0 + 1];
        int pr = d0 >> 1;
#pragma unroll
        for (int mt = 0; mt < 4; mt++)
#pragma unroll
            for (int half = 0; half < 2; half++) {
                int row = by + wm * 64 + mt * 16 + half * 8 + g;
                float r = ssv[mt][half];
                float2 cs = tab[(size_t)row * 64 + pr];
                float x0 = acc[mt][nt][half * 2] * (r * w0);
                float x1 = acc[mt][nt][half * 2 + 1] * (r * w1);
                float o0 = x0 * cs.x - x1 * cs.y;
                float o1 = x0 * cs.y + x1 * cs.x;
                if (z == 0) { o0 *= scale; o1 *= scale; }
                *(uint32_t*)(dst + (size_t)row * HID + bx + d0) = pack2h(o0, o1);
            }
    }
}

// ---------------- flash attention: single-term QK and PV --------------------
// Fixed-offset softmax P' = exp(S-4) (|S| <= 11.32 by Cauchy-Schwarz).
#define FS 136
#define QBYTES (128 * FS * 2)                  // 34816
#define KVSTAGE (2 * 64 * FS * 2)              // 34816 (K + V)
#define FLASH_SMEM (QBYTES + 4 * KVSTAGE)      // 174080
#define NIT (SEQ / 64)

__global__ __launch_bounds__(256) void flash_mma(
    const __half* __restrict__ Qh, const __half* __restrict__ Kh,
    const __half* __restrict__ Vh, __half* __restrict__ O)
{
    extern __shared__ __half sm[];

    const int tid  = threadIdx.x;
    const int warp = tid >> 5;
    const int lane = tid & 31;
    const int g    = lane >> 2;
    const int t    = lane & 3;
    const int h    = blockIdx.y;
    const int q0   = blockIdx.x * 128;

    const uint32_t base  = smem_u32(sm);
    const uint32_t qBase = base;

#pragma unroll
    for (int i = 0; i < 8; i++) {
        int v = tid + i * 256;
        int r = v >> 4, c = (v & 15) * 8;
        *(uint4*)(sm + r * FS + c) =
            *(const uint4*)(Qh + (size_t)(q0 + r) * HID + h * HD + c);
    }

    auto kv_load = [&](int s, int kt0) {
        uint32_t sb = base + QBYTES + (uint32_t)s * KVSTAGE;
#pragma unroll
        for (int t2 = 0; t2 < 2; t2++) {
            const char* src = (t2 == 0) ? (const char*)Kh : (const char*)Vh;
#pragma unroll
            for (int i = 0; i < 4; i++) {
                int v = tid + i * 256;
                int r = v >> 4, c = v & 15;
                cpasync16(sb + (uint32_t)(t2 * 64 * FS + r * FS) * 2 + c * 16,
                          src + ((size_t)(kt0 + r) * HID + h * HD) * 2 + c * 16);
            }
        }
    };

    const int wq = warp * 16;
    float o[16][4] = {};
    float l0s = 0.f, l1s = 0.f;

    const int mat  = lane >> 3;
    const int arow = (lane & 7) + 8 * (mat & 1);
    const int acol8 = 8 * (mat >> 1);
    const int brow = (lane & 7) + 8 * (mat >> 1);
    const int bcol8 = 8 * (mat & 1);
    const int vrow = (lane & 7) + 8 * (mat & 1);
    const int vcol8 = 8 * (mat >> 1);

    kv_load(0, 0);
    CP_COMMIT();
    kv_load(1, 64);
    CP_COMMIT();

    __syncthreads();
    uint32_t qf[8][4];
#pragma unroll
    for (int c = 0; c < 8; c++) {
        uint32_t aoff = ((wq + arow) * FS + c * 16 + acol8) * 2;
        ldsm4(qf[c], qBase + aoff);
    }

    for (int it = 0; it < NIT; it++) {
        if (it + 2 < NIT) {
            kv_load((it + 2) & 3, (it + 2) * 64);
            CP_COMMIT();
            CP_WAIT(2);
        } else if (it + 1 < NIT) {
            CP_WAIT(1);
        } else {
            CP_WAIT(0);
        }
        __syncthreads();

        const uint32_t sb = base + QBYTES + (uint32_t)(it & 3) * KVSTAGE;
        const uint32_t kBase = sb;
        const uint32_t vBase = sb + 64 * FS * 2;

        float S[8][4] = {};
#pragma unroll
        for (int c = 0; c < 8; c++) {
#pragma unroll
            for (int p = 0; p < 4; p++) {
                uint32_t boff = ((p * 16 + brow) * FS + c * 16 + bcol8) * 2;
                uint32_t k4[4];
                ldsm4(k4, kBase + boff);
                uint32_t k0[2] = {k4[0], k4[1]}, k1[2] = {k4[2], k4[3]};
                mma_f16(S[2 * p], qf[c], k0);
                mma_f16(S[2 * p + 1], qf[c], k1);
            }
        }

        uint32_t Ph0[8], Ph1[8];
        float s0 = 0.f, s1 = 0.f;
#pragma unroll
        for (int nt = 0; nt < 8; nt++) {
            float p00 = __expf(S[nt][0] - 4.0f);
            float p01 = __expf(S[nt][1] - 4.0f);
            float p10 = __expf(S[nt][2] - 4.0f);
            float p11 = __expf(S[nt][3] - 4.0f);
            s0 += p00 + p01;
            s1 += p10 + p11;
            Ph0[nt] = pack2h(p00, p01);
            Ph1[nt] = pack2h(p10, p11);
        }
        l0s += s0;
        l1s += s1;

#pragma unroll
        for (int c = 0; c < 4; c++) {
            uint32_t A_h[4] = {Ph0[2 * c], Ph1[2 * c], Ph0[2 * c + 1], Ph1[2 * c + 1]};
#pragma unroll
            for (int dd = 0; dd < 8; dd++) {
                uint32_t voff = ((c * 16 + vrow) * FS + dd * 16 + vcol8) * 2;
                uint32_t vh4[4];
                ldsm4t(vh4, vBase + voff);
                uint32_t vh0[2] = {vh4[0], vh4[1]}, vh1[2] = {vh4[2], vh4[3]};
                mma_f16(o[2 * dd], A_h, vh0);
                mma_f16(o[2 * dd + 1], A_h, vh1);
            }
        }
    }

    l0s += __shfl_xor_sync(0xffffffffu, l0s, 1);
    l0s += __shfl_xor_sync(0xffffffffu, l0s, 2);
    l1s += __shfl_xor_sync(0xffffffffu, l1s, 1);
    l1s += __shfl_xor_sync(0xffffffffu, l1s, 2);

    float inv0 = 1.0f / l0s, inv1 = 1.0f / l1s;
    int row0 = q0 + wq + g;
#pragma unroll
    for (int d = 0; d < 16; d++) {
        int col = h * HD + d * 8 + 2 * t;
        *(uint32_t*)(O + (size_t)row0 * HID + col) =
            pack2h(o[d][0] * inv0, o[d][1] * inv0);
        *(uint32_t*)(O + (size_t)(row0 + 8) * HID + col) =
            pack2h(o[d][2] * inv1, o[d][3] * inv1);
    }
}

// ---------------- launch ---------------------------------------------------
extern "C" void kernel_launch(void* const* d_in, const int* in_sizes, int n_in,
                              void* d_out, int out_size)
{
    const float* x   = (const float*)d_in[0];
    const int*   pos = (const int*)d_in[1];
    const float* wq  = (const float*)d_in[2];
    const float* wk  = (const float*)d_in[3];
    const float* wv  = (const float*)d_in[4];
    const float* wo  = (const float*)d_in[5];
    const float* qnw = (const float*)d_in[6];
    const float* knw = (const float*)d_in[7];
    float* out = (float*)d_out;

    __half *ah, *wh, *qh, *kh, *vh, *ch;
    float2* tab;
    cudaGetSymbolAddress((void**)&ah,  g_ah);
    cudaGetSymbolAddress((void**)&wh,  g_wh);
    cudaGetSymbolAddress((void**)&qh,  g_qh);
    cudaGetSymbolAddress((void**)&kh,  g_kh);
    cudaGetSymbolAddress((void**)&vh,  g_vh);
    cudaGetSymbolAddress((void**)&ch,  g_ch);
    cudaGetSymbolAddress((void**)&tab, g_tab);

    cudaFuncSetAttribute(gemm_f16,
                         cudaFuncAttributeMaxDynamicSharedMemorySize, GEMM_SMEM);
    cudaFuncSetAttribute(flash_mma,
                         cudaFuncAttributeMaxDynamicSharedMemorySize, FLASH_SMEM);

    const int NELEM = SEQ * HID;
    const size_t WSZ = (size_t)HID * HID;

    rope_tab<<<SEQ, 64>>>(pos, tab);
    conv_h<<<NELEM / 1024, 256>>>(x, ah, NELEM);
    conv_wt<<<dim3(HID / 32, HID / 32, 4), dim3(32, 8)>>>(wq, wk, wv, wo, wh);

    gemm_f16<<<dim3(HID / 128, SEQ / 256, 3), 512, GEMM_SMEM>>>(
        ah, wh, out /*unused*/, qh, kh, vh, tab, qnw, knw, 1);

    flash_mma<<<dim3(SEQ / 128, NH), 256, FLASH_SMEM>>>(qh, kh, vh, ch);

    gemm_f16<<<dim3(HID / 128, SEQ / 256, 1), 512, GEMM_SMEM>>>(
        ch, wh + 3 * WSZ, out, qh, kh, vh, tab, qnw, knw, 0);
}